// round 12
// baseline (speedup 1.0000x reference)
#include <cuda_runtime.h>
#include <math.h>
#include <stdint.h>

#define SEQL    4096
#define BATCHN  4
#define BL      (BATCHN*SEQL)       // 16384
#define DMODEL  192
#define DINNER  384
#define DSTATE  64
#define NHEADS  8
#define HEADDIM 48
#define CONVDIM 512
#define DINPROJ 904
#define NLAYERS 8
#define NCHUNK  64
#define CHUNKL  64

// ---------------- scratch (device globals) -------------------------------
__device__ float g_X[BL*DMODEL];
__device__ float g_ZX[BL*DINPROJ];
__device__ float g_CONV[BL*CONVDIM];
__device__ float g_DTDEC[BL*NHEADS*2];
__device__ float g_Y[BL*DINNER];
__device__ float g_O[BL*DMODEL];
__device__ float g_S[BATCHN*NHEADS*NCHUNK*HEADDIM*DSTATE];
__device__ float g_P[BATCHN*NHEADS*NCHUNK];
__device__ float g_LAM[BL*NHEADS];

__device__ __forceinline__ float sigf(float x){ return 1.f/(1.f+__expf(-x)); }

__device__ __forceinline__ float f2tf32(float x) {
    uint32_t o;
    asm("cvt.rna.tf32.f32 %0, %1;" : "=r"(o) : "f"(x));
    return __uint_as_float(o);
}

// ---------------- input linear -------------------------------------------
__global__ void k_lin_in(const float* __restrict__ inp,
                         const float* __restrict__ w,
                         const float* __restrict__ bias) {
    int idx = blockIdx.x*blockDim.x + threadIdx.x;
    if (idx >= BL*DMODEL) return;
    int d  = idx % DMODEL;
    int bl = idx / DMODEL;
    int b = bl / SEQL, l = bl % SEQL;
    const float* ip = inp + (size_t)b*3*SEQL + l;
    float acc = bias[d];
    acc = fmaf(ip[0],      w[d*3+0], acc);
    acc = fmaf(ip[SEQL],   w[d*3+1], acc);
    acc = fmaf(ip[2*SEQL], w[d*3+2], acc);
    g_X[idx] = fmaxf(acc, 0.f);
}

// ---------------- 3xTF32 GEMM, double-buffered, hi/lo packed -------------
#define SA(b,k,m) sA[(((b)*16+(k))*132)+(m)]
#define SB(b,k,m) sB[(((b)*16+(k))*132)+(m)]

__global__ __launch_bounds__(256, 2)
void k_mma(const float* __restrict__ W, int mode, int N, int K, int ldC) {
    const float* A;
    float* C;
    if (mode == 0) { A = g_X; C = g_ZX; } else { A = g_Y; C = g_O; }

    extern __shared__ float2 smem[];
    float2* sA = smem;
    float2* sB = smem + 2*16*132;

    const int bm = blockIdx.y * 128;
    const int bn = blockIdx.x * 128;
    const int tid  = threadIdx.x;
    const int lane = tid & 31;
    const int wid  = tid >> 5;
    const int wm = wid >> 2;
    const int wn = wid & 3;
    const int lg = lane >> 2;
    const int lt = lane & 3;

    float acc[4][4][4];
    #pragma unroll
    for (int i = 0; i < 4; i++)
        #pragma unroll
        for (int j = 0; j < 4; j++)
            #pragma unroll
            for (int r = 0; r < 4; r++) acc[i][j][r] = 0.f;

    const int fr = tid >> 1;
    const int fh = (tid & 1) * 8;
    const bool wvalid = (bn + fr) < N;
    const float* Ag = A + (size_t)(bm + fr)*K + fh;
    const float* Wg = wvalid ? (W + (size_t)(bn + fr)*K + fh) : W;

    float av[8], bv[8];
    const int KT = K / 16;

    {
        float4 t0 = *(const float4*)(Ag + 0);
        float4 t1 = *(const float4*)(Ag + 4);
        av[0]=t0.x; av[1]=t0.y; av[2]=t0.z; av[3]=t0.w;
        av[4]=t1.x; av[5]=t1.y; av[6]=t1.z; av[7]=t1.w;
        if (wvalid) {
            float4 u0 = *(const float4*)(Wg + 0);
            float4 u1 = *(const float4*)(Wg + 4);
            bv[0]=u0.x; bv[1]=u0.y; bv[2]=u0.z; bv[3]=u0.w;
            bv[4]=u1.x; bv[5]=u1.y; bv[6]=u1.z; bv[7]=u1.w;
        } else {
            #pragma unroll
            for (int q = 0; q < 8; q++) bv[q] = 0.f;
        }
    }
    #pragma unroll
    for (int q = 0; q < 8; q++) {
        float ah = f2tf32(av[q]);
        SA(0, fh+q, fr) = make_float2(ah, f2tf32(av[q] - ah));
        float bh = f2tf32(bv[q]);
        SB(0, fh+q, fr) = make_float2(bh, f2tf32(bv[q] - bh));
    }
    __syncthreads();

    for (int kt = 0; kt < KT; kt++) {
        const int buf = kt & 1;
        if (kt + 1 < KT) {
            const float* an = Ag + (kt+1)*16;
            float4 t0 = *(const float4*)(an + 0);
            float4 t1 = *(const float4*)(an + 4);
            av[0]=t0.x; av[1]=t0.y; av[2]=t0.z; av[3]=t0.w;
            av[4]=t1.x; av[5]=t1.y; av[6]=t1.z; av[7]=t1.w;
            if (wvalid) {
                const float* wv = Wg + (kt+1)*16;
                float4 u0 = *(const float4*)(wv + 0);
                float4 u1 = *(const float4*)(wv + 4);
                bv[0]=u0.x; bv[1]=u0.y; bv[2]=u0.z; bv[3]=u0.w;
                bv[4]=u1.x; bv[5]=u1.y; bv[6]=u1.z; bv[7]=u1.w;
            }
        }

        #pragma unroll
        for (int ks = 0; ks < 2; ks++) {
            const int kr = ks*8 + lt;
            float2 bf[4][2];
            #pragma unroll
            for (int j = 0; j < 4; j++) {
                int n0 = wn*32 + j*8 + lg;
                bf[j][0] = SB(buf, kr,   n0);
                bf[j][1] = SB(buf, kr+4, n0);
            }
            #pragma unroll
            for (int i = 0; i < 4; i++) {
                int m0 = wm*64 + i*16 + lg;
                float2 a0 = SA(buf, kr,   m0);
                float2 a1 = SA(buf, kr,   m0+8);
                float2 a2 = SA(buf, kr+4, m0);
                float2 a3 = SA(buf, kr+4, m0+8);
                uint32_t ah0 = __float_as_uint(a0.x), al0 = __float_as_uint(a0.y);
                uint32_t ah1 = __float_as_uint(a1.x), al1 = __float_as_uint(a1.y);
                uint32_t ah2 = __float_as_uint(a2.x), al2 = __float_as_uint(a2.y);
                uint32_t ah3 = __float_as_uint(a3.x), al3 = __float_as_uint(a3.y);
                #pragma unroll
                for (int j = 0; j < 4; j++) {
                    uint32_t bh0 = __float_as_uint(bf[j][0].x);
                    uint32_t bh1 = __float_as_uint(bf[j][1].x);
                    uint32_t bl0 = __float_as_uint(bf[j][0].y);
                    uint32_t bl1 = __float_as_uint(bf[j][1].y);
                    asm volatile(
                        "mma.sync.aligned.m16n8k8.row.col.f32.tf32.tf32.f32 "
                        "{%0,%1,%2,%3}, {%4,%5,%6,%7}, {%8,%9}, {%0,%1,%2,%3};"
                        : "+f"(acc[i][j][0]), "+f"(acc[i][j][1]),
                          "+f"(acc[i][j][2]), "+f"(acc[i][j][3])
                        : "r"(al0), "r"(al1), "r"(al2), "r"(al3),
                          "r"(bh0), "r"(bh1));
                    asm volatile(
                        "mma.sync.aligned.m16n8k8.row.col.f32.tf32.tf32.f32 "
                        "{%0,%1,%2,%3}, {%4,%5,%6,%7}, {%8,%9}, {%0,%1,%2,%3};"
                        : "+f"(acc[i][j][0]), "+f"(acc[i][j][1]),
                          "+f"(acc[i][j][2]), "+f"(acc[i][j][3])
                        : "r"(ah0), "r"(ah1), "r"(ah2), "r"(ah3),
                          "r"(bl0), "r"(bl1));
                    asm volatile(
                        "mma.sync.aligned.m16n8k8.row.col.f32.tf32.tf32.f32 "
                        "{%0,%1,%2,%3}, {%4,%5,%6,%7}, {%8,%9}, {%0,%1,%2,%3};"
                        : "+f"(acc[i][j][0]), "+f"(acc[i][j][1]),
                          "+f"(acc[i][j][2]), "+f"(acc[i][j][3])
                        : "r"(ah0), "r"(ah1), "r"(ah2), "r"(ah3),
                          "r"(bh0), "r"(bh1));
                }
            }
        }

        if (kt + 1 < KT) {
            const int nb = 1 - buf;
            #pragma unroll
            for (int q = 0; q < 8; q++) {
                float ah = f2tf32(av[q]);
                SA(nb, fh+q, fr) = make_float2(ah, f2tf32(av[q] - ah));
                float bh = f2tf32(bv[q]);
                SB(nb, fh+q, fr) = make_float2(bh, f2tf32(bv[q] - bh));
            }
        }
        __syncthreads();
    }

    #pragma unroll
    for (int i = 0; i < 4; i++) {
        int m = bm + wm*64 + i*16 + lg;
        #pragma unroll
        for (int j = 0; j < 4; j++) {
            int n = bn + wn*32 + j*8 + 2*lt;
            if (n < N) {
                *(float2*)&C[(size_t)m*ldC + n] =
                    make_float2(acc[i][j][0], acc[i][j][1]);
                *(float2*)&C[(size_t)(m+8)*ldC + n] =
                    make_float2(acc[i][j][2], acc[i][j][3]);
            }
        }
    }
}
#define MMA_SMEM (2*2*16*132*sizeof(float2))

// ---------------- dt prep: EXACT fp32 dot + softplus + decay -------------
__global__ __launch_bounds__(256)
void k_dtprep(const float* __restrict__ dt_bias,
              const float* __restrict__ A_log,
              const float* __restrict__ in_w_layer) {
    int bl   = blockIdx.x*8 + (threadIdx.x >> 5);
    int lane = threadIdx.x & 31;
    if (bl >= BL) return;
    const float* xr = g_X + (size_t)bl*DMODEL;
    float x[6];
    #pragma unroll
    for (int r = 0; r < 6; r++) x[r] = xr[lane + 32*r];
    #pragma unroll
    for (int h = 0; h < NHEADS; h++) {
        const float* w = in_w_layer + (size_t)(896 + h)*DMODEL;
        float s = 0.f;
        #pragma unroll
        for (int r = 0; r < 6; r++) s = fmaf(x[r], w[lane + 32*r], s);
        #pragma unroll
        for (int o = 16; o > 0; o >>= 1) s += __shfl_xor_sync(0xffffffffu, s, o);
        if (lane == h) {
            float raw = s + dt_bias[h];
            float dt = (raw > 20.f) ? raw : log1pf(__expf(raw));
            float Ah = -__expf(A_log[h]);
            g_DTDEC[bl*16 + 2*h    ] = dt;
            g_DTDEC[bl*16 + 2*h + 1] = __expf(dt * Ah);
        }
    }
}

// ---------------- causal conv4 + silu ------------------------------------
__global__ void k_conv(const float* __restrict__ conv_w,
                       const float* __restrict__ conv_b) {
    int idx = blockIdx.x*blockDim.x + threadIdx.x;
    if (idx >= BL*CONVDIM) return;
    int c  = idx & (CONVDIM-1);
    int bl = idx >> 9;
    int l  = bl & (SEQL-1);
    float acc = conv_b[c];
    const float* base = &g_ZX[(size_t)bl*DINPROJ + 384 + c];
    #pragma unroll
    for (int k = 0; k < 4; k++) {
        int ll = l - 3 + k;
        if (ll >= 0)
            acc = fmaf(base[(ptrdiff_t)(k-3)*DINPROJ], conv_w[c*4 + k], acc);
    }
    g_CONV[idx] = acc * sigf(acc);
}

// ================= matmul-form chunk scan =================================
// one block (256 thr) per (b,h,ck).
// M[t][s] = (C_t . B_s) * exp(L_t - L_s) * dt_s  (s<=t),  Y = M @ X + D*x
// end state S[p][n] = sum_s exp(L63-L_s)*dt_s * X[s][p]*B[s][n]
// XOR-swizzled quads in sB/sC avoid bank conflicts on row-strided f4 loads.
#define SROW 68
#define SQ(row, q) ((row)*SROW + ((((q) ^ ((row) & 15))) << 2))
#define SCAN_SMEM ((3*64*SROW + 4*64) * 4)   // 53248 B

__global__ __launch_bounds__(256, 4)
void k_scan_mm(const float* __restrict__ A_log, const float* __restrict__ Dvec) {
    extern __shared__ float sm[];
    float* sB  = sm;                   // [64][68] swizzled (B rows)
    float* sC  = sB + 64*SROW;         // [64][68] swizzled C; later plain X
    float* sM  = sC + 64*SROW;         // [64][68] plain
    float* sdt = sM + 64*SROW;         // [64]
    float* sdA = sdt + 64;             // [64]
    float* sL  = sdA + 64;             // [64]
    float* sw  = sL + 64;              // [64]

    int ck = blockIdx.x & (NCHUNK-1);
    int bh = blockIdx.x >> 6;
    int h  = bh & 7, b = bh >> 3;
    int bl0 = b*SEQL + ck*CHUNKL;
    int tid = threadIdx.x;

    const float* convb = g_CONV + (size_t)bl0*CONVDIM;

    // stage B (swizzled), C (swizzled), dt
    for (int q = tid; q < 64*64; q += 256) {
        int s = q >> 6, n = q & 63;
        float vb = convb[(size_t)s*CONVDIM + 384 + n];
        float vc = convb[(size_t)s*CONVDIM + 448 + n];
        int off = SQ(s, n >> 2) + (n & 3);
        sB[off] = vb;
        sC[off] = vc;
    }
    if (tid < 64) {
        float dt = g_DTDEC[(size_t)(bl0 + tid)*16 + 2*h];
        float A  = -__expf(A_log[h]);
        sdt[tid] = dt;
        float da = dt * A;
        sdA[tid] = da;
        sL[tid]  = da;
    }
    __syncthreads();

    // Kogge-Stone cumsum of dtA -> L (inclusive)
    #pragma unroll
    for (int off = 1; off < 64; off <<= 1) {
        float add = 0.f;
        if (tid < 64 && tid >= off) add = sL[tid - off];
        __syncthreads();
        if (tid < 64 && tid >= off) sL[tid] += add;
        __syncthreads();
    }
    if (tid < 64) {
        float Lt = sL[tid];
        g_LAM[(size_t)(bl0 + tid)*NHEADS + h] = __expf(Lt);
        sw[tid] = __expf(sL[63] - Lt) * sdt[tid];
        if (tid == 63) g_P[bh*NCHUNK + ck] = __expf(Lt);
    }
    __syncthreads();

    // --- G = C . B^T  -> M with mask/decay/dt ---
    {
        int tx = tid & 15, ty = tid >> 4;
        int t0 = ty*4, s0 = tx*4;
        float acc[4][4];
        #pragma unroll
        for (int i = 0; i < 4; i++)
            #pragma unroll
            for (int j = 0; j < 4; j++) acc[i][j] = 0.f;

        #pragma unroll 4
        for (int q = 0; q < 16; q++) {
            float4 cv[4], bv[4];
            #pragma unroll
            for (int i = 0; i < 4; i++)
                cv[i] = *(const float4*)&sC[SQ(t0+i, q)];
            #pragma unroll
            for (int j = 0; j < 4; j++)
                bv[j] = *(const float4*)&sB[SQ(s0+j, q)];
            #pragma unroll
            for (int i = 0; i < 4; i++)
                #pragma unroll
                for (int j = 0; j < 4; j++) {
                    acc[i][j] = fmaf(cv[i].x, bv[j].x, acc[i][j]);
                    acc[i][j] = fmaf(cv[i].y, bv[j].y, acc[i][j]);
                    acc[i][j] = fmaf(cv[i].z, bv[j].z, acc[i][j]);
                    acc[i][j] = fmaf(cv[i].w, bv[j].w, acc[i][j]);
                }
        }
        #pragma unroll
        for (int i = 0; i < 4; i++) {
            int t = t0 + i;
            float Lt = sL[t];
            #pragma unroll
            for (int j = 0; j < 4; j++) {
                int s = s0 + j;
                float m = 0.f;
                if (s <= t)
                    m = acc[i][j] * __expf(Lt - sL[s]) * sdt[s];
                sM[t*SROW + s] = m;
            }
        }
    }
    __syncthreads();

    // stage X (plain layout) into sC (C no longer needed)
    for (int q = tid; q < 64*48; q += 256) {
        int t = q / 48, p = q % 48;
        sC[t*SROW + p] = convb[(size_t)t*CONVDIM + h*HEADDIM + p];
    }
    __syncthreads();

    // --- Y = M @ X + D*x ---
    {
        int tx = tid & 15, ty = tid >> 4;
        int t0 = ty*4, p0 = tx*3;
        float acc[4][3];
        #pragma unroll
        for (int i = 0; i < 4; i++)
            #pragma unroll
            for (int j = 0; j < 3; j++) acc[i][j] = 0.f;

        #pragma unroll 2
        for (int s0 = 0; s0 < 64; s0 += 4) {
            float4 mv[4];
            #pragma unroll
            for (int i = 0; i < 4; i++)
                mv[i] = *(const float4*)&sM[(t0+i)*SROW + s0];
            float xv[4][3];
            #pragma unroll
            for (int k = 0; k < 4; k++)
                #pragma unroll
                for (int j = 0; j < 3; j++)
                    xv[k][j] = sC[(s0+k)*SROW + p0 + j];
            #pragma unroll
            for (int i = 0; i < 4; i++)
                #pragma unroll
                for (int j = 0; j < 3; j++) {
                    acc[i][j] = fmaf(mv[i].x, xv[0][j], acc[i][j]);
                    acc[i][j] = fmaf(mv[i].y, xv[1][j], acc[i][j]);
                    acc[i][j] = fmaf(mv[i].z, xv[2][j], acc[i][j]);
                    acc[i][j] = fmaf(mv[i].w, xv[3][j], acc[i][j]);
                }
        }
        float Dh = Dvec[h];
        #pragma unroll
        for (int i = 0; i < 4; i++) {
            int t = t0 + i;
            float* yr = g_Y + (size_t)(bl0 + t)*DINNER + h*HEADDIM + p0;
            #pragma unroll
            for (int j = 0; j < 3; j++)
                yr[j] = fmaf(Dh, sC[t*SROW + p0 + j], acc[i][j]);
        }
    }

    // --- end state S[p][n] = sum_s w_s X[s][p] B[s][n] ---
    {
        int tx = tid & 15, ty = tid >> 4;
        int n0 = tx*4, p0 = ty*3;
        float acc[3][4];
        #pragma unroll
        for (int j = 0; j < 3; j++)
            #pragma unroll
            for (int k = 0; k < 4; k++) acc[j][k] = 0.f;

        #pragma unroll 4
        for (int s = 0; s < 64; s++) {
            float w = sw[s];
            float xw[3];
            #pragma unroll
            for (int j = 0; j < 3; j++)
                xw[j] = w * sC[s*SROW + p0 + j];
            float4 bv = *(const float4*)&sB[SQ(s, tx)];
            #pragma unroll
            for (int j = 0; j < 3; j++) {
                acc[j][0] = fmaf(xw[j], bv.x, acc[j][0]);
                acc[j][1] = fmaf(xw[j], bv.y, acc[j][1]);
                acc[j][2] = fmaf(xw[j], bv.z, acc[j][2]);
                acc[j][3] = fmaf(xw[j], bv.w, acc[j][3]);
            }
        }
        float* Sb = g_S + (((size_t)bh*NCHUNK + ck)*HEADDIM)*DSTATE;
        #pragma unroll
        for (int j = 0; j < 3; j++)
            *(float4*)&Sb[(size_t)(p0 + j)*DSTATE + n0] =
                make_float4(acc[j][0], acc[j][1], acc[j][2], acc[j][3]);
    }
}

// inter-chunk recurrence — register-staged
__global__ __launch_bounds__(256)
void k_chunk_seq() {
    int idx = blockIdx.x*blockDim.x + threadIdx.x;
    if (idx >= BATCHN*NHEADS*HEADDIM*DSTATE) return;
    int pn = idx % (HEADDIM*DSTATE);
    int bh = idx / (HEADDIM*DSTATE);
    const float* P = g_P + bh*NCHUNK;
    float* S = g_S + (size_t)bh*NCHUNK*HEADDIM*DSTATE + pn;

    float v[NCHUNK];
    #pragma unroll
    for (int k = 0; k < NCHUNK; k++)
        v[k] = __ldg(S + (size_t)k*HEADDIM*DSTATE);

    float h = 0.f;
    #pragma unroll
    for (int k = 0; k < NCHUNK; k++) {
        float s = v[k];
        v[k] = h;
        h = fmaf(h, P[k], s);
    }

    #pragma unroll
    for (int k = 0; k < NCHUNK; k++)
        S[(size_t)k*HEADDIM*DSTATE] = v[k];
}

// correction: Y[t][p] += Lam_t * sum_n C[t][n] * Hinit[p][n]
__global__ __launch_bounds__(256)
void k_corr() {
    __shared__ float Cs[64][68];
    __shared__ float Hs[64][49];
    __shared__ float Ls[64];

    int ck = blockIdx.x % NCHUNK;
    int bh = blockIdx.x / NCHUNK;
    int h  = bh & 7, b = bh >> 3;
    int bl0 = b*SEQL + ck*CHUNKL;
    int tid = threadIdx.x;

    #pragma unroll
    for (int q = tid; q < 64*16; q += 256) {
        int t  = q >> 4;
        int n4 = (q & 15) << 2;
        float4 v = *(const float4*)&g_CONV[(size_t)(bl0 + t)*CONVDIM + 448 + n4];
        Cs[n4+0][t] = v.x; Cs[n4+1][t] = v.y;
        Cs[n4+2][t] = v.z; Cs[n4+3][t] = v.w;
    }
    const float* Sb = g_S + (((size_t)bh*NCHUNK + ck)*HEADDIM)*DSTATE;
    #pragma unroll
    for (int q = tid; q < 48*16; q += 256) {
        int p  = q >> 4;
        int n4 = (q & 15) << 2;
        float4 v = *(const float4*)&Sb[(size_t)p*DSTATE + n4];
        Hs[n4+0][p] = v.x; Hs[n4+1][p] = v.y;
        Hs[n4+2][p] = v.z; Hs[n4+3][p] = v.w;
    }
    if (tid < 64)
        Ls[tid] = g_LAM[(size_t)(bl0 + tid)*NHEADS + h];
    __syncthreads();

    int tx = tid & 15, ty = tid >> 4;
    int pp = tx*3, tt = ty*4;

    float acc[4][3];
    #pragma unroll
    for (int i = 0; i < 4; i++)
        #pragma unroll
        for (int j = 0; j < 3; j++) acc[i][j] = 0.f;

    #pragma unroll 4
    for (int n = 0; n < 64; n++) {
        float4 c = *(const float4*)&Cs[n][tt];
        float ca[4] = {c.x, c.y, c.z, c.w};
        float hh0 = Hs[n][pp], hh1 = Hs[n][pp+1], hh2 = Hs[n][pp+2];
        #pragma unroll
        for (int i = 0; i < 4; i++) {
            acc[i][0] = fmaf(ca[i], hh0, acc[i][0]);
            acc[i][1] = fmaf(ca[i], hh1, acc[i][1]);
            acc[i][2] = fmaf(ca[i], hh2, acc[i][2]);
        }
    }

    #pragma unroll
    for (int i = 0; i < 4; i++) {
        float lam = Ls[tt + i];
        float* yr = g_Y + (size_t)(bl0 + tt + i)*DINNER + h*HEADDIM + pp;
        #pragma unroll
        for (int j = 0; j < 3; j++)
            yr[j] = fmaf(lam, acc[i][j], yr[j]);
    }
}

// ---------------- gated RMSNorm ------------------------------------------
__global__ __launch_bounds__(128)
void k_gated_rms(const float* __restrict__ norm_w) {
    int bl = blockIdx.x;
    int t  = threadIdx.x;
    int lane = t & 31, wid = t >> 5;
    __shared__ float sh[4];
    float v[3];
    float ss = 0.f;
    #pragma unroll
    for (int j = 0; j < 3; j++) {
        int d = t + j*128;
        float y = g_Y[(size_t)bl*DINNER + d];
        float z = g_ZX[(size_t)bl*DINPROJ + d];
        y *= z * sigf(z);
        v[j] = y;
        ss = fmaf(y, y, ss);
    }
    #pragma unroll
    for (int o = 16; o > 0; o >>= 1) ss += __shfl_xor_sync(0xffffffffu, ss, o);
    if (lane == 0) sh[wid] = ss;
    __syncthreads();
    ss = sh[0] + sh[1] + sh[2] + sh[3];
    float rms = rsqrtf(ss * (1.f/DINNER) + 1e-5f);
    #pragma unroll
    for (int j = 0; j < 3; j++) {
        int d = t + j*128;
        g_Y[(size_t)bl*DINNER + d] = v[j] * rms * norm_w[d];
    }
}

// ---------------- residual add + layernorm -> X --------------------------
__global__ __launch_bounds__(192)
void k_res_ln(const float* __restrict__ ln_w, const float* __restrict__ ln_b) {
    int bl = blockIdx.x;
    int d  = threadIdx.x;
    int lane = d & 31, wid = d >> 5;
    __shared__ float shs[6], shq[6];
    float x = g_O[(size_t)bl*DMODEL + d] + g_X[(size_t)bl*DMODEL + d];
    float s = x, q = x*x;
    #pragma unroll
    for (int o = 16; o > 0; o >>= 1) {
        s += __shfl_xor_sync(0xffffffffu, s, o);
        q += __shfl_xor_sync(0xffffffffu, q, o);
    }
    if (lane == 0) { shs[wid] = s; shq[wid] = q; }
    __syncthreads();
    s = 0.f; q = 0.f;
    #pragma unroll
    for (int i = 0; i < 6; i++) { s += shs[i]; q += shq[i]; }
    float mu  = s * (1.f/DMODEL);
    float var = q * (1.f/DMODEL) - mu*mu;
    g_X[(size_t)bl*DMODEL + d] = (x - mu) * rsqrtf(var + 1e-5f) * ln_w[d] + ln_b[d];
}

// ---------------- output linear ------------------------------------------
__global__ __launch_bounds__(192)
void k_final(const float* __restrict__ w, const float* __restrict__ bias,
             float* __restrict__ out) {
    int bl = blockIdx.x;
    int d  = threadIdx.x;
    int lane = d & 31, wid = d >> 5;
    int b = bl / SEQL, l = bl % SEQL;
    __shared__ float sh[6][4];
    float x = g_X[(size_t)bl*DMODEL + d];
    float p0 = x * w[0*DMODEL + d];
    float p1 = x * w[1*DMODEL + d];
    float p2 = x * w[2*DMODEL + d];
    float p3 = x * w[3*DMODEL + d];
    #pragma unroll
    for (int o = 16; o > 0; o >>= 1) {
        p0 += __shfl_xor_sync(0xffffffffu, p0, o);
        p1 += __shfl_xor_sync(0xffffffffu, p1, o);
        p2 += __shfl_xor_sync(0xffffffffu, p2, o);
        p3 += __shfl_xor_sync(0xffffffffu, p3, o);
    }
    if (lane == 0) { sh[wid][0]=p0; sh[wid][1]=p1; sh[wid][2]=p2; sh[wid][3]=p3; }
    __syncthreads();
    if (d < 4) {
        float s = 0.f;
        #pragma unroll
        for (int i = 0; i < 6; i++) s += sh[i][d];
        out[(size_t)b*4*SEQL + (size_t)d*SEQL + l] = s + bias[d];
    }
}

// ---------------- driver --------------------------------------------------
extern "C" void kernel_launch(void* const* d_in, const int* in_sizes, int n_in,
                              void* d_out, int out_size) {
    const float* inp      = (const float*)d_in[0];
    const float* lin_in_w = (const float*)d_in[1];
    const float* lin_in_b = (const float*)d_in[2];
    const float* in_w     = (const float*)d_in[3];
    const float* conv_w   = (const float*)d_in[4];
    const float* conv_b   = (const float*)d_in[5];
    const float* dt_bias  = (const float*)d_in[6];
    const float* A_log    = (const float*)d_in[7];
    const float* Dv       = (const float*)d_in[8];
    const float* norm_w   = (const float*)d_in[9];
    const float* out_w    = (const float*)d_in[10];
    const float* ln_w     = (const float*)d_in[11];
    const float* ln_b     = (const float*)d_in[12];
    const float* lo_w     = (const float*)d_in[13];
    const float* lo_b     = (const float*)d_in[14];
    float* out = (float*)d_out;

    static bool attr_set = false;
    if (!attr_set) {
        cudaFuncSetAttribute(k_mma, cudaFuncAttributeMaxDynamicSharedMemorySize,
                             (int)MMA_SMEM);
        cudaFuncSetAttribute(k_scan_mm, cudaFuncAttributeMaxDynamicSharedMemorySize,
                             (int)SCAN_SMEM);
        attr_set = true;
    }

    const int scan_blocks = BATCHN*NHEADS*NCHUNK;   // 2048
    const int corr_blocks = BATCHN*NHEADS*NCHUNK;

    k_lin_in<<<(BL*DMODEL + 255)/256, 256>>>(inp, lin_in_w, lin_in_b);

    for (int layer = 0; layer < NLAYERS; layer++) {
        const float* in_w_l = in_w + (size_t)layer*DINPROJ*DMODEL;
        {
            dim3 grid(896/128, BL/128);
            k_mma<<<grid, 256, MMA_SMEM>>>(in_w_l, 0, 896, DMODEL, DINPROJ);
        }
        k_dtprep<<<BL/8, 256>>>(dt_bias + layer*NHEADS,
                                A_log + layer*NHEADS, in_w_l);
        k_conv<<<(BL*CONVDIM + 255)/256, 256>>>(conv_w + (size_t)layer*CONVDIM*4,
                                                conv_b + (size_t)layer*CONVDIM);
        k_scan_mm<<<scan_blocks, 256, SCAN_SMEM>>>(A_log + layer*NHEADS,
                                                   Dv + layer*NHEADS);
        k_chunk_seq<<<(BATCHN*NHEADS*HEADDIM*DSTATE + 255)/256, 256>>>();
        k_corr<<<corr_blocks, 256>>>();
        k_gated_rms<<<BL, 128>>>(norm_w + (size_t)layer*DINNER);
        {
            dim3 grid((DMODEL + 127)/128, BL/128);
            k_mma<<<grid, 256, MMA_SMEM>>>(out_w + (size_t)layer*DMODEL*DINNER, 1,
                                           DMODEL, DINNER, DMODEL);
        }
        k_res_ln<<<BL, 192>>>(ln_w + (size_t)layer*DMODEL,
                              ln_b + (size_t)layer*DMODEL);
    }

    k_final<<<BL, 192>>>(lo_w, lo_b, out);
}

// round 13
// speedup vs baseline: 1.1126x; 1.1126x over previous
#include <cuda_runtime.h>
#include <math.h>
#include <stdint.h>

#define SEQL    4096
#define BATCHN  4
#define BL      (BATCHN*SEQL)       // 16384
#define DMODEL  192
#define DINNER  384
#define DSTATE  64
#define NHEADS  8
#define HEADDIM 48
#define CONVDIM 512
#define DINPROJ 904
#define NLAYERS 8
#define NCHUNK  64
#define CHUNKL  64

// ---------------- scratch (device globals) -------------------------------
__device__ float g_X[BL*DMODEL];
__device__ float g_ZX[BL*DINPROJ];
__device__ float g_CONV[BL*CONVDIM];
__device__ float g_DTDEC[BL*NHEADS*2];
__device__ float g_Y[BL*DINNER];
__device__ float g_O[BL*DMODEL];
__device__ float g_S[BATCHN*NHEADS*NCHUNK*HEADDIM*DSTATE];
__device__ float g_P[BATCHN*NHEADS*NCHUNK];
__device__ float g_LAM[BL*NHEADS];

__device__ __forceinline__ float sigf(float x){ return 1.f/(1.f+__expf(-x)); }

__device__ __forceinline__ float f2tf32(float x) {
    uint32_t o;
    asm("cvt.rna.tf32.f32 %0, %1;" : "=r"(o) : "f"(x));
    return __uint_as_float(o);
}

// ---------------- input linear -------------------------------------------
__global__ void k_lin_in(const float* __restrict__ inp,
                         const float* __restrict__ w,
                         const float* __restrict__ bias) {
    int idx = blockIdx.x*blockDim.x + threadIdx.x;
    if (idx >= BL*DMODEL) return;
    int d  = idx % DMODEL;
    int bl = idx / DMODEL;
    int b = bl / SEQL, l = bl % SEQL;
    const float* ip = inp + (size_t)b*3*SEQL + l;
    float acc = bias[d];
    acc = fmaf(ip[0],      w[d*3+0], acc);
    acc = fmaf(ip[SEQL],   w[d*3+1], acc);
    acc = fmaf(ip[2*SEQL], w[d*3+2], acc);
    g_X[idx] = fmaxf(acc, 0.f);
}

// ---------------- 3xTF32 GEMM, double-buffered, hi/lo packed -------------
#define SA(b,k,m) sA[(((b)*16+(k))*132)+(m)]
#define SB(b,k,m) sB[(((b)*16+(k))*132)+(m)]

__global__ __launch_bounds__(256, 2)
void k_mma(const float* __restrict__ W, int mode, int N, int K, int ldC) {
    const float* A;
    float* C;
    if (mode == 0) { A = g_X; C = g_ZX; } else { A = g_Y; C = g_O; }

    extern __shared__ float2 smem[];
    float2* sA = smem;
    float2* sB = smem + 2*16*132;

    const int bm = blockIdx.y * 128;
    const int bn = blockIdx.x * 128;
    const int tid  = threadIdx.x;
    const int lane = tid & 31;
    const int wid  = tid >> 5;
    const int wm = wid >> 2;
    const int wn = wid & 3;
    const int lg = lane >> 2;
    const int lt = lane & 3;

    float acc[4][4][4];
    #pragma unroll
    for (int i = 0; i < 4; i++)
        #pragma unroll
        for (int j = 0; j < 4; j++)
            #pragma unroll
            for (int r = 0; r < 4; r++) acc[i][j][r] = 0.f;

    const int fr = tid >> 1;
    const int fh = (tid & 1) * 8;
    const bool wvalid = (bn + fr) < N;
    const float* Ag = A + (size_t)(bm + fr)*K + fh;
    const float* Wg = wvalid ? (W + (size_t)(bn + fr)*K + fh) : W;

    float av[8], bv[8];
    const int KT = K / 16;

    {
        float4 t0 = *(const float4*)(Ag + 0);
        float4 t1 = *(const float4*)(Ag + 4);
        av[0]=t0.x; av[1]=t0.y; av[2]=t0.z; av[3]=t0.w;
        av[4]=t1.x; av[5]=t1.y; av[6]=t1.z; av[7]=t1.w;
        if (wvalid) {
            float4 u0 = *(const float4*)(Wg + 0);
            float4 u1 = *(const float4*)(Wg + 4);
            bv[0]=u0.x; bv[1]=u0.y; bv[2]=u0.z; bv[3]=u0.w;
            bv[4]=u1.x; bv[5]=u1.y; bv[6]=u1.z; bv[7]=u1.w;
        } else {
            #pragma unroll
            for (int q = 0; q < 8; q++) bv[q] = 0.f;
        }
    }
    #pragma unroll
    for (int q = 0; q < 8; q++) {
        float ah = f2tf32(av[q]);
        SA(0, fh+q, fr) = make_float2(ah, f2tf32(av[q] - ah));
        float bh = f2tf32(bv[q]);
        SB(0, fh+q, fr) = make_float2(bh, f2tf32(bv[q] - bh));
    }
    __syncthreads();

    for (int kt = 0; kt < KT; kt++) {
        const int buf = kt & 1;
        if (kt + 1 < KT) {
            const float* an = Ag + (kt+1)*16;
            float4 t0 = *(const float4*)(an + 0);
            float4 t1 = *(const float4*)(an + 4);
            av[0]=t0.x; av[1]=t0.y; av[2]=t0.z; av[3]=t0.w;
            av[4]=t1.x; av[5]=t1.y; av[6]=t1.z; av[7]=t1.w;
            if (wvalid) {
                const float* wv = Wg + (kt+1)*16;
                float4 u0 = *(const float4*)(wv + 0);
                float4 u1 = *(const float4*)(wv + 4);
                bv[0]=u0.x; bv[1]=u0.y; bv[2]=u0.z; bv[3]=u0.w;
                bv[4]=u1.x; bv[5]=u1.y; bv[6]=u1.z; bv[7]=u1.w;
            }
        }

        #pragma unroll
        for (int ks = 0; ks < 2; ks++) {
            const int kr = ks*8 + lt;
            float2 bf[4][2];
            #pragma unroll
            for (int j = 0; j < 4; j++) {
                int n0 = wn*32 + j*8 + lg;
                bf[j][0] = SB(buf, kr,   n0);
                bf[j][1] = SB(buf, kr+4, n0);
            }
            #pragma unroll
            for (int i = 0; i < 4; i++) {
                int m0 = wm*64 + i*16 + lg;
                float2 a0 = SA(buf, kr,   m0);
                float2 a1 = SA(buf, kr,   m0+8);
                float2 a2 = SA(buf, kr+4, m0);
                float2 a3 = SA(buf, kr+4, m0+8);
                uint32_t ah0 = __float_as_uint(a0.x), al0 = __float_as_uint(a0.y);
                uint32_t ah1 = __float_as_uint(a1.x), al1 = __float_as_uint(a1.y);
                uint32_t ah2 = __float_as_uint(a2.x), al2 = __float_as_uint(a2.y);
                uint32_t ah3 = __float_as_uint(a3.x), al3 = __float_as_uint(a3.y);
                #pragma unroll
                for (int j = 0; j < 4; j++) {
                    uint32_t bh0 = __float_as_uint(bf[j][0].x);
                    uint32_t bh1 = __float_as_uint(bf[j][1].x);
                    uint32_t bl0 = __float_as_uint(bf[j][0].y);
                    uint32_t bl1 = __float_as_uint(bf[j][1].y);
                    asm volatile(
                        "mma.sync.aligned.m16n8k8.row.col.f32.tf32.tf32.f32 "
                        "{%0,%1,%2,%3}, {%4,%5,%6,%7}, {%8,%9}, {%0,%1,%2,%3};"
                        : "+f"(acc[i][j][0]), "+f"(acc[i][j][1]),
                          "+f"(acc[i][j][2]), "+f"(acc[i][j][3])
                        : "r"(al0), "r"(al1), "r"(al2), "r"(al3),
                          "r"(bh0), "r"(bh1));
                    asm volatile(
                        "mma.sync.aligned.m16n8k8.row.col.f32.tf32.tf32.f32 "
                        "{%0,%1,%2,%3}, {%4,%5,%6,%7}, {%8,%9}, {%0,%1,%2,%3};"
                        : "+f"(acc[i][j][0]), "+f"(acc[i][j][1]),
                          "+f"(acc[i][j][2]), "+f"(acc[i][j][3])
                        : "r"(ah0), "r"(ah1), "r"(ah2), "r"(ah3),
                          "r"(bl0), "r"(bl1));
                    asm volatile(
                        "mma.sync.aligned.m16n8k8.row.col.f32.tf32.tf32.f32 "
                        "{%0,%1,%2,%3}, {%4,%5,%6,%7}, {%8,%9}, {%0,%1,%2,%3};"
                        : "+f"(acc[i][j][0]), "+f"(acc[i][j][1]),
                          "+f"(acc[i][j][2]), "+f"(acc[i][j][3])
                        : "r"(ah0), "r"(ah1), "r"(ah2), "r"(ah3),
                          "r"(bh0), "r"(bh1));
                }
            }
        }

        if (kt + 1 < KT) {
            const int nb = 1 - buf;
            #pragma unroll
            for (int q = 0; q < 8; q++) {
                float ah = f2tf32(av[q]);
                SA(nb, fh+q, fr) = make_float2(ah, f2tf32(av[q] - ah));
                float bh = f2tf32(bv[q]);
                SB(nb, fh+q, fr) = make_float2(bh, f2tf32(bv[q] - bh));
            }
        }
        __syncthreads();
    }

    #pragma unroll
    for (int i = 0; i < 4; i++) {
        int m = bm + wm*64 + i*16 + lg;
        #pragma unroll
        for (int j = 0; j < 4; j++) {
            int n = bn + wn*32 + j*8 + 2*lt;
            if (n < N) {
                *(float2*)&C[(size_t)m*ldC + n] =
                    make_float2(acc[i][j][0], acc[i][j][1]);
                *(float2*)&C[(size_t)(m+8)*ldC + n] =
                    make_float2(acc[i][j][2], acc[i][j][3]);
            }
        }
    }
}
#define MMA_SMEM (2*2*16*132*sizeof(float2))

// -------- fused: causal conv4+silu  AND  dtprep (appended blocks) --------
#define CONV_BLKS ((BL*CONVDIM + 255)/256)   // 32768

__global__ __launch_bounds__(256)
void k_convdt(const float* __restrict__ conv_w, const float* __restrict__ conv_b,
              const float* __restrict__ dt_bias, const float* __restrict__ A_log,
              const float* __restrict__ in_w_layer) {
    if (blockIdx.x >= CONV_BLKS) {
        // ---- dtprep path: warp per token ----
        int bl   = (blockIdx.x - CONV_BLKS)*8 + ((int)threadIdx.x >> 5);
        int lane = threadIdx.x & 31;
        const float* xr = g_X + (size_t)bl*DMODEL;
        float x[6];
        #pragma unroll
        for (int r = 0; r < 6; r++) x[r] = xr[lane + 32*r];
        #pragma unroll
        for (int h = 0; h < NHEADS; h++) {
            const float* w = in_w_layer + (size_t)(896 + h)*DMODEL;
            float s = 0.f;
            #pragma unroll
            for (int r = 0; r < 6; r++) s = fmaf(x[r], w[lane + 32*r], s);
            #pragma unroll
            for (int o = 16; o > 0; o >>= 1)
                s += __shfl_xor_sync(0xffffffffu, s, o);
            if (lane == h) {
                float raw = s + dt_bias[h];
                float dt = (raw > 20.f) ? raw : log1pf(__expf(raw));
                float Ah = -__expf(A_log[h]);
                g_DTDEC[bl*16 + 2*h    ] = dt;
                g_DTDEC[bl*16 + 2*h + 1] = __expf(dt * Ah);
            }
        }
        return;
    }
    // ---- conv path ----
    int idx = blockIdx.x*blockDim.x + threadIdx.x;
    int c  = idx & (CONVDIM-1);
    int bl = idx >> 9;
    int l  = bl & (SEQL-1);
    float acc = conv_b[c];
    const float* base = &g_ZX[(size_t)bl*DINPROJ + 384 + c];
    #pragma unroll
    for (int k = 0; k < 4; k++) {
        int ll = l - 3 + k;
        if (ll >= 0)
            acc = fmaf(base[(ptrdiff_t)(k-3)*DINPROJ], conv_w[c*4 + k], acc);
    }
    g_CONV[idx] = acc * sigf(acc);
}

// ================= block-cooperative chunked scan =========================
#define SCAN_SMEM (64*128*4 + 64*48*4 + 64*48*4 + 64*8)   // 57856 B

__global__ __launch_bounds__(384, 3)   // cap regs at 56 -> 3 blocks/SM
void k_scan_blk(const float* __restrict__ Dvec) {
    extern __shared__ float sm[];
    float*  sBC  = sm;
    float*  sX   = sBC + 64*128;
    float*  sY   = sX  + 64*48;
    float2* sdde = (float2*)(sY + 64*48);

    int ck = blockIdx.x & (NCHUNK-1);
    int bh = blockIdx.x >> 6;
    int h  = bh & 7, b = bh >> 3;
    int bl0 = b*SEQL + ck*CHUNKL;
    int tid  = threadIdx.x;
    int lane = tid & 31;
    int wid  = tid >> 5;
    int p0   = wid*4;

    const float* convb = g_CONV + (size_t)bl0*CONVDIM;

    for (int q = tid; q < 64*32; q += 384) {
        int t = q >> 5, c4 = (q & 31) << 2;
        *(float4*)&sBC[t*128 + c4] =
            *(const float4*)&convb[(size_t)t*CONVDIM + 384 + c4];
    }
    for (int q = tid; q < 64*12; q += 384) {
        int t = q / 12, c4 = (q % 12) << 2;
        *(float4*)&sX[t*48 + c4] =
            *(const float4*)&convb[(size_t)t*CONVDIM + h*HEADDIM + c4];
    }
    if (tid < 64)
        sdde[tid] = *(const float2*)&g_DTDEC[(size_t)(bl0 + tid)*16 + 2*h];
    __syncthreads();

    if (tid == 0) {
        float pr = 1.f;
        for (int t = 0; t < CHUNKL; t++) {
            pr *= sdde[t].y;
            g_LAM[(size_t)(bl0 + t)*NHEADS + h] = pr;
        }
        g_P[bh*NCHUNK + ck] = pr;
    }

    const float Dh = Dvec[h];
    const int g    = lane >> 3;
    const int poff = (g >> 1) | ((g & 1) << 1);
    const bool st  = (lane & 7) == 0;

    float h0[4], h1[4];
    #pragma unroll
    for (int i = 0; i < 4; i++) { h0[i] = 0.f; h1[i] = 0.f; }

    #pragma unroll 2
    for (int t = 0; t < CHUNKL; t++) {
        float2 dde = sdde[t];
        float4 xv  = *(const float4*)&sX[t*48 + p0];
        float2 Bv  = *(const float2*)&sBC[t*128 + 2*lane];
        float2 Cv  = *(const float2*)&sBC[t*128 + 64 + 2*lane];
        float bx = dde.x * Bv.x;
        float by = dde.x * Bv.y;
        float xa[4] = {xv.x, xv.y, xv.z, xv.w};
        float y[4];
        #pragma unroll
        for (int i = 0; i < 4; i++) {
            h0[i] = fmaf(h0[i], dde.y, xa[i]*bx);
            h1[i] = fmaf(h1[i], dde.y, xa[i]*by);
            y[i]  = fmaf(h0[i], Cv.x, h1[i]*Cv.y);
        }
        #pragma unroll
        for (int i = 0; i < 4; i++)
            y[i] += __shfl_xor_sync(0xffffffffu, y[i], 16);
        float za = (lane & 16) ? y[1] : y[0];
        float zb = (lane & 16) ? y[3] : y[2];
        za += __shfl_xor_sync(0xffffffffu, za, 8);
        zb += __shfl_xor_sync(0xffffffffu, zb, 8);
        float wv = (lane & 8) ? zb : za;
        wv += __shfl_xor_sync(0xffffffffu, wv, 4);
        wv += __shfl_xor_sync(0xffffffffu, wv, 2);
        wv += __shfl_xor_sync(0xffffffffu, wv, 1);
        if (st) {
            float xs = (g == 0) ? xa[0] : (g == 1) ? xa[2]
                     : (g == 2) ? xa[1] : xa[3];
            sY[t*48 + p0 + poff] = fmaf(Dh, xs, wv);
        }
    }

    float* S = &g_S[((((size_t)bh*NCHUNK + ck)*HEADDIM) + p0)*DSTATE + 2*lane];
    #pragma unroll
    for (int i = 0; i < 4; i++)
        *(float2*)(S + (size_t)i*DSTATE) = make_float2(h0[i], h1[i]);

    __syncthreads();
    for (int q = tid; q < 64*12; q += 384) {
        int t = q / 12, c4 = (q % 12) << 2;
        *(float4*)&g_Y[(size_t)(bl0 + t)*DINNER + h*HEADDIM + c4] =
            *(const float4*)&sY[t*48 + c4];
    }
}

// inter-chunk recurrence — register-staged
__global__ __launch_bounds__(256)
void k_chunk_seq() {
    int idx = blockIdx.x*blockDim.x + threadIdx.x;
    if (idx >= BATCHN*NHEADS*HEADDIM*DSTATE) return;
    int pn = idx % (HEADDIM*DSTATE);
    int bh = idx / (HEADDIM*DSTATE);
    const float* P = g_P + bh*NCHUNK;
    float* S = g_S + (size_t)bh*NCHUNK*HEADDIM*DSTATE + pn;

    float v[NCHUNK];
    #pragma unroll
    for (int k = 0; k < NCHUNK; k++)
        v[k] = __ldg(S + (size_t)k*HEADDIM*DSTATE);

    float h = 0.f;
    #pragma unroll
    for (int k = 0; k < NCHUNK; k++) {
        float s = v[k];
        v[k] = h;
        h = fmaf(h, P[k], s);
    }

    #pragma unroll
    for (int k = 0; k < NCHUNK; k++)
        S[(size_t)k*HEADDIM*DSTATE] = v[k];
}

// correction: Y[t][p] += Lam_t * sum_n C[t][n] * Hinit[p][n]
__global__ __launch_bounds__(256)
void k_corr() {
    __shared__ float Cs[64][68];
    __shared__ float Hs[64][49];
    __shared__ float Ls[64];

    int ck = blockIdx.x % NCHUNK;
    int bh = blockIdx.x / NCHUNK;
    int h  = bh & 7, b = bh >> 3;
    int bl0 = b*SEQL + ck*CHUNKL;
    int tid = threadIdx.x;

    #pragma unroll
    for (int q = tid; q < 64*16; q += 256) {
        int t  = q >> 4;
        int n4 = (q & 15) << 2;
        float4 v = *(const float4*)&g_CONV[(size_t)(bl0 + t)*CONVDIM + 448 + n4];
        Cs[n4+0][t] = v.x; Cs[n4+1][t] = v.y;
        Cs[n4+2][t] = v.z; Cs[n4+3][t] = v.w;
    }
    const float* Sb = g_S + (((size_t)bh*NCHUNK + ck)*HEADDIM)*DSTATE;
    #pragma unroll
    for (int q = tid; q < 48*16; q += 256) {
        int p  = q >> 4;
        int n4 = (q & 15) << 2;
        float4 v = *(const float4*)&Sb[(size_t)p*DSTATE + n4];
        Hs[n4+0][p] = v.x; Hs[n4+1][p] = v.y;
        Hs[n4+2][p] = v.z; Hs[n4+3][p] = v.w;
    }
    if (tid < 64)
        Ls[tid] = g_LAM[(size_t)(bl0 + tid)*NHEADS + h];
    __syncthreads();

    int tx = tid & 15, ty = tid >> 4;
    int pp = tx*3, tt = ty*4;

    float acc[4][3];
    #pragma unroll
    for (int i = 0; i < 4; i++)
        #pragma unroll
        for (int j = 0; j < 3; j++) acc[i][j] = 0.f;

    #pragma unroll 4
    for (int n = 0; n < 64; n++) {
        float4 c = *(const float4*)&Cs[n][tt];
        float ca[4] = {c.x, c.y, c.z, c.w};
        float hh0 = Hs[n][pp], hh1 = Hs[n][pp+1], hh2 = Hs[n][pp+2];
        #pragma unroll
        for (int i = 0; i < 4; i++) {
            acc[i][0] = fmaf(ca[i], hh0, acc[i][0]);
            acc[i][1] = fmaf(ca[i], hh1, acc[i][1]);
            acc[i][2] = fmaf(ca[i], hh2, acc[i][2]);
        }
    }

    #pragma unroll
    for (int i = 0; i < 4; i++) {
        float lam = Ls[tt + i];
        float* yr = g_Y + (size_t)(bl0 + tt + i)*DINNER + h*HEADDIM + pp;
        #pragma unroll
        for (int j = 0; j < 3; j++)
            yr[j] = fmaf(lam, acc[i][j], yr[j]);
    }
}

// ---------------- gated RMSNorm ------------------------------------------
__global__ __launch_bounds__(128)
void k_gated_rms(const float* __restrict__ norm_w) {
    int bl = blockIdx.x;
    int t  = threadIdx.x;
    int lane = t & 31, wid = t >> 5;
    __shared__ float sh[4];
    float v[3];
    float ss = 0.f;
    #pragma unroll
    for (int j = 0; j < 3; j++) {
        int d = t + j*128;
        float y = g_Y[(size_t)bl*DINNER + d];
        float z = g_ZX[(size_t)bl*DINPROJ + d];
        y *= z * sigf(z);
        v[j] = y;
        ss = fmaf(y, y, ss);
    }
    #pragma unroll
    for (int o = 16; o > 0; o >>= 1) ss += __shfl_xor_sync(0xffffffffu, ss, o);
    if (lane == 0) sh[wid] = ss;
    __syncthreads();
    ss = sh[0] + sh[1] + sh[2] + sh[3];
    float rms = rsqrtf(ss * (1.f/DINNER) + 1e-5f);
    #pragma unroll
    for (int j = 0; j < 3; j++) {
        int d = t + j*128;
        g_Y[(size_t)bl*DINNER + d] = v[j] * rms * norm_w[d];
    }
}

// ---------------- residual add + layernorm -> X --------------------------
__global__ __launch_bounds__(192)
void k_res_ln(const float* __restrict__ ln_w, const float* __restrict__ ln_b) {
    int bl = blockIdx.x;
    int d  = threadIdx.x;
    int lane = d & 31, wid = d >> 5;
    __shared__ float shs[6], shq[6];
    float x = g_O[(size_t)bl*DMODEL + d] + g_X[(size_t)bl*DMODEL + d];
    float s = x, q = x*x;
    #pragma unroll
    for (int o = 16; o > 0; o >>= 1) {
        s += __shfl_xor_sync(0xffffffffu, s, o);
        q += __shfl_xor_sync(0xffffffffu, q, o);
    }
    if (lane == 0) { shs[wid] = s; shq[wid] = q; }
    __syncthreads();
    s = 0.f; q = 0.f;
    #pragma unroll
    for (int i = 0; i < 6; i++) { s += shs[i]; q += shq[i]; }
    float mu  = s * (1.f/DMODEL);
    float var = q * (1.f/DMODEL) - mu*mu;
    g_X[(size_t)bl*DMODEL + d] = (x - mu) * rsqrtf(var + 1e-5f) * ln_w[d] + ln_b[d];
}

// ---------------- output linear ------------------------------------------
__global__ __launch_bounds__(192)
void k_final(const float* __restrict__ w, const float* __restrict__ bias,
             float* __restrict__ out) {
    int bl = blockIdx.x;
    int d  = threadIdx.x;
    int lane = d & 31, wid = d >> 5;
    int b = bl / SEQL, l = bl % SEQL;
    __shared__ float sh[6][4];
    float x = g_X[(size_t)bl*DMODEL + d];
    float p0 = x * w[0*DMODEL + d];
    float p1 = x * w[1*DMODEL + d];
    float p2 = x * w[2*DMODEL + d];
    float p3 = x * w[3*DMODEL + d];
    #pragma unroll
    for (int o = 16; o > 0; o >>= 1) {
        p0 += __shfl_xor_sync(0xffffffffu, p0, o);
        p1 += __shfl_xor_sync(0xffffffffu, p1, o);
        p2 += __shfl_xor_sync(0xffffffffu, p2, o);
        p3 += __shfl_xor_sync(0xffffffffu, p3, o);
    }
    if (lane == 0) { sh[wid][0]=p0; sh[wid][1]=p1; sh[wid][2]=p2; sh[wid][3]=p3; }
    __syncthreads();
    if (d < 4) {
        float s = 0.f;
        #pragma unroll
        for (int i = 0; i < 6; i++) s += sh[i][d];
        out[(size_t)b*4*SEQL + (size_t)d*SEQL + l] = s + bias[d];
    }
}

// ---------------- driver --------------------------------------------------
extern "C" void kernel_launch(void* const* d_in, const int* in_sizes, int n_in,
                              void* d_out, int out_size) {
    const float* inp      = (const float*)d_in[0];
    const float* lin_in_w = (const float*)d_in[1];
    const float* lin_in_b = (const float*)d_in[2];
    const float* in_w     = (const float*)d_in[3];
    const float* conv_w   = (const float*)d_in[4];
    const float* conv_b   = (const float*)d_in[5];
    const float* dt_bias  = (const float*)d_in[6];
    const float* A_log    = (const float*)d_in[7];
    const float* Dv       = (const float*)d_in[8];
    const float* norm_w   = (const float*)d_in[9];
    const float* out_w    = (const float*)d_in[10];
    const float* ln_w     = (const float*)d_in[11];
    const float* ln_b     = (const float*)d_in[12];
    const float* lo_w     = (const float*)d_in[13];
    const float* lo_b     = (const float*)d_in[14];
    float* out = (float*)d_out;

    static bool attr_set = false;
    if (!attr_set) {
        cudaFuncSetAttribute(k_mma, cudaFuncAttributeMaxDynamicSharedMemorySize,
                             (int)MMA_SMEM);
        cudaFuncSetAttribute(k_scan_blk, cudaFuncAttributeMaxDynamicSharedMemorySize,
                             (int)SCAN_SMEM);
        attr_set = true;
    }

    const int scan_blocks = BATCHN*NHEADS*NCHUNK;   // 2048
    const int corr_blocks = BATCHN*NHEADS*NCHUNK;

    k_lin_in<<<(BL*DMODEL + 255)/256, 256>>>(inp, lin_in_w, lin_in_b);

    for (int layer = 0; layer < NLAYERS; layer++) {
        const float* in_w_l = in_w + (size_t)layer*DINPROJ*DMODEL;
        {
            // N=896 logical cols (dt recomputed exactly in fused dtprep), ldC=904
            dim3 grid(896/128, BL/128);
            k_mma<<<grid, 256, MMA_SMEM>>>(in_w_l, 0, 896, DMODEL, DINPROJ);
        }
        // fused conv + dtprep (independent workloads, one launch)
        k_convdt<<<CONV_BLKS + BL/8, 256>>>(
            conv_w + (size_t)layer*CONVDIM*4,
            conv_b + (size_t)layer*CONVDIM,
            dt_bias + layer*NHEADS,
            A_log + layer*NHEADS,
            in_w_l);
        k_scan_blk<<<scan_blocks, 384, SCAN_SMEM>>>(Dv + layer*NHEADS);
        k_chunk_seq<<<(BATCHN*NHEADS*HEADDIM*DSTATE + 255)/256, 256>>>();
        k_corr<<<corr_blocks, 256>>>();
        k_gated_rms<<<BL, 128>>>(norm_w + (size_t)layer*DINNER);
        {
            dim3 grid((DMODEL + 127)/128, BL/128);
            k_mma<<<grid, 256, MMA_SMEM>>>(out_w + (size_t)layer*DMODEL*DINNER, 1,
                                           DMODEL, DINNER, DMODEL);
        }
        k_res_ln<<<BL, 192>>>(ln_w + (size_t)layer*DMODEL,
                              ln_b + (size_t)layer*DMODEL);
    }

    k_final<<<BL, 192>>>(lo_w, lo_b, out);
}

// round 14
// speedup vs baseline: 1.1474x; 1.0313x over previous
#include <cuda_runtime.h>
#include <math.h>
#include <stdint.h>

#define SEQL    4096
#define BATCHN  4
#define BL      (BATCHN*SEQL)       // 16384
#define DMODEL  192
#define DINNER  384
#define DSTATE  64
#define NHEADS  8
#define HEADDIM 48
#define CONVDIM 512
#define DINPROJ 904
#define NLAYERS 8
#define NCHUNK  64
#define CHUNKL  64

// ---------------- scratch (device globals) -------------------------------
__device__ float g_X[BL*DMODEL];
__device__ float g_ZX[BL*DINPROJ];
__device__ float g_CONV[BL*CONVDIM];
__device__ float g_DTDEC[BL*NHEADS*2];
__device__ float g_Y[BL*DINNER];
__device__ float g_O[BL*DMODEL];
__device__ float g_S[BATCHN*NHEADS*NCHUNK*HEADDIM*DSTATE];
__device__ float g_P[BATCHN*NHEADS*NCHUNK];
__device__ float g_LAM[BL*NHEADS];

__device__ __forceinline__ float sigf(float x){ return 1.f/(1.f+__expf(-x)); }

__device__ __forceinline__ float f2tf32(float x) {
    uint32_t o;
    asm("cvt.rna.tf32.f32 %0, %1;" : "=r"(o) : "f"(x));
    return __uint_as_float(o);
}

// ---------------- input linear -------------------------------------------
__global__ void k_lin_in(const float* __restrict__ inp,
                         const float* __restrict__ w,
                         const float* __restrict__ bias) {
    int idx = blockIdx.x*blockDim.x + threadIdx.x;
    if (idx >= BL*DMODEL) return;
    int d  = idx % DMODEL;
    int bl = idx / DMODEL;
    int b = bl / SEQL, l = bl % SEQL;
    const float* ip = inp + (size_t)b*3*SEQL + l;
    float acc = bias[d];
    acc = fmaf(ip[0],      w[d*3+0], acc);
    acc = fmaf(ip[SEQL],   w[d*3+1], acc);
    acc = fmaf(ip[2*SEQL], w[d*3+2], acc);
    g_X[idx] = fmaxf(acc, 0.f);
}

// ---------------- 3xTF32 GEMM, double-buffered, hi/lo packed -------------
#define SA(b,k,m) sA[(((b)*16+(k))*132)+(m)]
#define SB(b,k,m) sB[(((b)*16+(k))*132)+(m)]

__global__ __launch_bounds__(256, 2)
void k_mma(const float* __restrict__ W, int mode, int N, int K, int ldC) {
    const float* A;
    float* C;
    if (mode == 0) { A = g_X; C = g_ZX; } else { A = g_Y; C = g_O; }

    extern __shared__ float2 smem[];
    float2* sA = smem;
    float2* sB = smem + 2*16*132;

    const int bm = blockIdx.y * 128;
    const int bn = blockIdx.x * 128;
    const int tid  = threadIdx.x;
    const int lane = tid & 31;
    const int wid  = tid >> 5;
    const int wm = wid >> 2;
    const int wn = wid & 3;
    const int lg = lane >> 2;
    const int lt = lane & 3;

    float acc[4][4][4];
    #pragma unroll
    for (int i = 0; i < 4; i++)
        #pragma unroll
        for (int j = 0; j < 4; j++)
            #pragma unroll
            for (int r = 0; r < 4; r++) acc[i][j][r] = 0.f;

    const int fr = tid >> 1;
    const int fh = (tid & 1) * 8;
    const bool wvalid = (bn + fr) < N;
    const float* Ag = A + (size_t)(bm + fr)*K + fh;
    const float* Wg = wvalid ? (W + (size_t)(bn + fr)*K + fh) : W;

    float av[8], bv[8];
    const int KT = K / 16;

    {
        float4 t0 = *(const float4*)(Ag + 0);
        float4 t1 = *(const float4*)(Ag + 4);
        av[0]=t0.x; av[1]=t0.y; av[2]=t0.z; av[3]=t0.w;
        av[4]=t1.x; av[5]=t1.y; av[6]=t1.z; av[7]=t1.w;
        if (wvalid) {
            float4 u0 = *(const float4*)(Wg + 0);
            float4 u1 = *(const float4*)(Wg + 4);
            bv[0]=u0.x; bv[1]=u0.y; bv[2]=u0.z; bv[3]=u0.w;
            bv[4]=u1.x; bv[5]=u1.y; bv[6]=u1.z; bv[7]=u1.w;
        } else {
            #pragma unroll
            for (int q = 0; q < 8; q++) bv[q] = 0.f;
        }
    }
    #pragma unroll
    for (int q = 0; q < 8; q++) {
        float ah = f2tf32(av[q]);
        SA(0, fh+q, fr) = make_float2(ah, f2tf32(av[q] - ah));
        float bh = f2tf32(bv[q]);
        SB(0, fh+q, fr) = make_float2(bh, f2tf32(bv[q] - bh));
    }
    __syncthreads();

    for (int kt = 0; kt < KT; kt++) {
        const int buf = kt & 1;
        if (kt + 1 < KT) {
            const float* an = Ag + (kt+1)*16;
            float4 t0 = *(const float4*)(an + 0);
            float4 t1 = *(const float4*)(an + 4);
            av[0]=t0.x; av[1]=t0.y; av[2]=t0.z; av[3]=t0.w;
            av[4]=t1.x; av[5]=t1.y; av[6]=t1.z; av[7]=t1.w;
            if (wvalid) {
                const float* wv = Wg + (kt+1)*16;
                float4 u0 = *(const float4*)(wv + 0);
                float4 u1 = *(const float4*)(wv + 4);
                bv[0]=u0.x; bv[1]=u0.y; bv[2]=u0.z; bv[3]=u0.w;
                bv[4]=u1.x; bv[5]=u1.y; bv[6]=u1.z; bv[7]=u1.w;
            }
        }

        #pragma unroll
        for (int ks = 0; ks < 2; ks++) {
            const int kr = ks*8 + lt;
            float2 bf[4][2];
            #pragma unroll
            for (int j = 0; j < 4; j++) {
                int n0 = wn*32 + j*8 + lg;
                bf[j][0] = SB(buf, kr,   n0);
                bf[j][1] = SB(buf, kr+4, n0);
            }
            #pragma unroll
            for (int i = 0; i < 4; i++) {
                int m0 = wm*64 + i*16 + lg;
                float2 a0 = SA(buf, kr,   m0);
                float2 a1 = SA(buf, kr,   m0+8);
                float2 a2 = SA(buf, kr+4, m0);
                float2 a3 = SA(buf, kr+4, m0+8);
                uint32_t ah0 = __float_as_uint(a0.x), al0 = __float_as_uint(a0.y);
                uint32_t ah1 = __float_as_uint(a1.x), al1 = __float_as_uint(a1.y);
                uint32_t ah2 = __float_as_uint(a2.x), al2 = __float_as_uint(a2.y);
                uint32_t ah3 = __float_as_uint(a3.x), al3 = __float_as_uint(a3.y);
                #pragma unroll
                for (int j = 0; j < 4; j++) {
                    uint32_t bh0 = __float_as_uint(bf[j][0].x);
                    uint32_t bh1 = __float_as_uint(bf[j][1].x);
                    uint32_t bl0 = __float_as_uint(bf[j][0].y);
                    uint32_t bl1 = __float_as_uint(bf[j][1].y);
                    asm volatile(
                        "mma.sync.aligned.m16n8k8.row.col.f32.tf32.tf32.f32 "
                        "{%0,%1,%2,%3}, {%4,%5,%6,%7}, {%8,%9}, {%0,%1,%2,%3};"
                        : "+f"(acc[i][j][0]), "+f"(acc[i][j][1]),
                          "+f"(acc[i][j][2]), "+f"(acc[i][j][3])
                        : "r"(al0), "r"(al1), "r"(al2), "r"(al3),
                          "r"(bh0), "r"(bh1));
                    asm volatile(
                        "mma.sync.aligned.m16n8k8.row.col.f32.tf32.tf32.f32 "
                        "{%0,%1,%2,%3}, {%4,%5,%6,%7}, {%8,%9}, {%0,%1,%2,%3};"
                        : "+f"(acc[i][j][0]), "+f"(acc[i][j][1]),
                          "+f"(acc[i][j][2]), "+f"(acc[i][j][3])
                        : "r"(ah0), "r"(ah1), "r"(ah2), "r"(ah3),
                          "r"(bl0), "r"(bl1));
                    asm volatile(
                        "mma.sync.aligned.m16n8k8.row.col.f32.tf32.tf32.f32 "
                        "{%0,%1,%2,%3}, {%4,%5,%6,%7}, {%8,%9}, {%0,%1,%2,%3};"
                        : "+f"(acc[i][j][0]), "+f"(acc[i][j][1]),
                          "+f"(acc[i][j][2]), "+f"(acc[i][j][3])
                        : "r"(ah0), "r"(ah1), "r"(ah2), "r"(ah3),
                          "r"(bh0), "r"(bh1));
                }
            }
        }

        if (kt + 1 < KT) {
            const int nb = 1 - buf;
            #pragma unroll
            for (int q = 0; q < 8; q++) {
                float ah = f2tf32(av[q]);
                SA(nb, fh+q, fr) = make_float2(ah, f2tf32(av[q] - ah));
                float bh = f2tf32(bv[q]);
                SB(nb, fh+q, fr) = make_float2(bh, f2tf32(bv[q] - bh));
            }
        }
        __syncthreads();
    }

    #pragma unroll
    for (int i = 0; i < 4; i++) {
        int m = bm + wm*64 + i*16 + lg;
        #pragma unroll
        for (int j = 0; j < 4; j++) {
            int n = bn + wn*32 + j*8 + 2*lt;
            if (n < N) {
                *(float2*)&C[(size_t)m*ldC + n] =
                    make_float2(acc[i][j][0], acc[i][j][1]);
                *(float2*)&C[(size_t)(m+8)*ldC + n] =
                    make_float2(acc[i][j][2], acc[i][j][3]);
            }
        }
    }
}
#define MMA_SMEM (2*2*16*132*sizeof(float2))

// -------- fused: causal conv4+silu  AND  dtprep (appended blocks) --------
#define CONV_BLKS ((BL*CONVDIM + 255)/256)   // 32768

__global__ __launch_bounds__(256)
void k_convdt(const float* __restrict__ conv_w, const float* __restrict__ conv_b,
              const float* __restrict__ dt_bias, const float* __restrict__ A_log,
              const float* __restrict__ in_w_layer) {
    if (blockIdx.x >= CONV_BLKS) {
        int bl   = (blockIdx.x - CONV_BLKS)*8 + ((int)threadIdx.x >> 5);
        int lane = threadIdx.x & 31;
        const float* xr = g_X + (size_t)bl*DMODEL;
        float x[6];
        #pragma unroll
        for (int r = 0; r < 6; r++) x[r] = xr[lane + 32*r];
        #pragma unroll
        for (int h = 0; h < NHEADS; h++) {
            const float* w = in_w_layer + (size_t)(896 + h)*DMODEL;
            float s = 0.f;
            #pragma unroll
            for (int r = 0; r < 6; r++) s = fmaf(x[r], w[lane + 32*r], s);
            #pragma unroll
            for (int o = 16; o > 0; o >>= 1)
                s += __shfl_xor_sync(0xffffffffu, s, o);
            if (lane == h) {
                float raw = s + dt_bias[h];
                float dt = (raw > 20.f) ? raw : log1pf(__expf(raw));
                float Ah = -__expf(A_log[h]);
                g_DTDEC[bl*16 + 2*h    ] = dt;
                g_DTDEC[bl*16 + 2*h + 1] = __expf(dt * Ah);
            }
        }
        return;
    }
    int idx = blockIdx.x*blockDim.x + threadIdx.x;
    int c  = idx & (CONVDIM-1);
    int bl = idx >> 9;
    int l  = bl & (SEQL-1);
    float acc = conv_b[c];
    const float* base = &g_ZX[(size_t)bl*DINPROJ + 384 + c];
    #pragma unroll
    for (int k = 0; k < 4; k++) {
        int ll = l - 3 + k;
        if (ll >= 0)
            acc = fmaf(base[(ptrdiff_t)(k-3)*DINPROJ], conv_w[c*4 + k], acc);
    }
    g_CONV[idx] = acc * sigf(acc);
}

// ================= block-cooperative chunked scan =========================
// 4 blocks/SM: no sY staging (direct predicated y store), regs capped 42.
#define SCAN_SMEM (64*128*4 + 64*48*4 + 64*8)   // 45568 B

__global__ __launch_bounds__(384, 4)
void k_scan_blk(const float* __restrict__ Dvec) {
    extern __shared__ float sm[];
    float*  sBC  = sm;                 // [64][128]
    float*  sX   = sBC + 64*128;       // [64][48]
    float2* sdde = (float2*)(sX + 64*48);  // [64]

    int ck = blockIdx.x & (NCHUNK-1);
    int bh = blockIdx.x >> 6;
    int h  = bh & 7, b = bh >> 3;
    int bl0 = b*SEQL + ck*CHUNKL;
    int tid  = threadIdx.x;
    int lane = tid & 31;
    int wid  = tid >> 5;
    int p0   = wid*4;

    const float* convb = g_CONV + (size_t)bl0*CONVDIM;

    for (int q = tid; q < 64*32; q += 384) {
        int t = q >> 5, c4 = (q & 31) << 2;
        *(float4*)&sBC[t*128 + c4] =
            *(const float4*)&convb[(size_t)t*CONVDIM + 384 + c4];
    }
    for (int q = tid; q < 64*12; q += 384) {
        int t = q / 12, c4 = (q % 12) << 2;
        *(float4*)&sX[t*48 + c4] =
            *(const float4*)&convb[(size_t)t*CONVDIM + h*HEADDIM + c4];
    }
    if (tid < 64)
        sdde[tid] = *(const float2*)&g_DTDEC[(size_t)(bl0 + tid)*16 + 2*h];
    __syncthreads();

    if (tid == 0) {
        float pr = 1.f;
        for (int t = 0; t < CHUNKL; t++) {
            pr *= sdde[t].y;
            g_LAM[(size_t)(bl0 + t)*NHEADS + h] = pr;
        }
        g_P[bh*NCHUNK + ck] = pr;
    }

    const float Dh = Dvec[h];
    const int g    = lane >> 3;
    const int poff = (g >> 1) | ((g & 1) << 1);
    const bool st  = (lane & 7) == 0;
    // direct y store pointer for this electing lane
    float* yo = g_Y + (size_t)bl0*DINNER + h*HEADDIM + p0 + poff;

    float h0[4], h1[4];
    #pragma unroll
    for (int i = 0; i < 4; i++) { h0[i] = 0.f; h1[i] = 0.f; }

    #pragma unroll 2
    for (int t = 0; t < CHUNKL; t++) {
        float2 dde = sdde[t];
        float4 xv  = *(const float4*)&sX[t*48 + p0];
        float2 Bv  = *(const float2*)&sBC[t*128 + 2*lane];
        float2 Cv  = *(const float2*)&sBC[t*128 + 64 + 2*lane];
        float bx = dde.x * Bv.x;
        float by = dde.x * Bv.y;
        float xa[4] = {xv.x, xv.y, xv.z, xv.w};
        float y[4];
        #pragma unroll
        for (int i = 0; i < 4; i++) {
            h0[i] = fmaf(h0[i], dde.y, xa[i]*bx);
            h1[i] = fmaf(h1[i], dde.y, xa[i]*by);
            y[i]  = fmaf(h0[i], Cv.x, h1[i]*Cv.y);
        }
        #pragma unroll
        for (int i = 0; i < 4; i++)
            y[i] += __shfl_xor_sync(0xffffffffu, y[i], 16);
        float za = (lane & 16) ? y[1] : y[0];
        float zb = (lane & 16) ? y[3] : y[2];
        za += __shfl_xor_sync(0xffffffffu, za, 8);
        zb += __shfl_xor_sync(0xffffffffu, zb, 8);
        float wv = (lane & 8) ? zb : za;
        wv += __shfl_xor_sync(0xffffffffu, wv, 4);
        wv += __shfl_xor_sync(0xffffffffu, wv, 2);
        wv += __shfl_xor_sync(0xffffffffu, wv, 1);
        if (st) {
            float xs = (g == 0) ? xa[0] : (g == 1) ? xa[2]
                     : (g == 2) ? xa[1] : xa[3];
            *yo = fmaf(Dh, xs, wv);
        }
        yo += DINNER;
    }

    float* S = &g_S[((((size_t)bh*NCHUNK + ck)*HEADDIM) + p0)*DSTATE + 2*lane];
    #pragma unroll
    for (int i = 0; i < 4; i++)
        *(float2*)(S + (size_t)i*DSTATE) = make_float2(h0[i], h1[i]);
}

// inter-chunk recurrence — register-staged
__global__ __launch_bounds__(256)
void k_chunk_seq() {
    int idx = blockIdx.x*blockDim.x + threadIdx.x;
    if (idx >= BATCHN*NHEADS*HEADDIM*DSTATE) return;
    int pn = idx % (HEADDIM*DSTATE);
    int bh = idx / (HEADDIM*DSTATE);
    const float* P = g_P + bh*NCHUNK;
    float* S = g_S + (size_t)bh*NCHUNK*HEADDIM*DSTATE + pn;

    float v[NCHUNK];
    #pragma unroll
    for (int k = 0; k < NCHUNK; k++)
        v[k] = __ldg(S + (size_t)k*HEADDIM*DSTATE);

    float h = 0.f;
    #pragma unroll
    for (int k = 0; k < NCHUNK; k++) {
        float s = v[k];
        v[k] = h;
        h = fmaf(h, P[k], s);
    }

    #pragma unroll
    for (int k = 0; k < NCHUNK; k++)
        S[(size_t)k*HEADDIM*DSTATE] = v[k];
}

// correction: Y[t][p] += Lam_t * sum_n C[t][n] * Hinit[p][n]
__global__ __launch_bounds__(256)
void k_corr() {
    __shared__ float Cs[64][68];
    __shared__ float Hs[64][49];
    __shared__ float Ls[64];

    int ck = blockIdx.x % NCHUNK;
    int bh = blockIdx.x / NCHUNK;
    int h  = bh & 7, b = bh >> 3;
    int bl0 = b*SEQL + ck*CHUNKL;
    int tid = threadIdx.x;

    #pragma unroll
    for (int q = tid; q < 64*16; q += 256) {
        int t  = q >> 4;
        int n4 = (q & 15) << 2;
        float4 v = *(const float4*)&g_CONV[(size_t)(bl0 + t)*CONVDIM + 448 + n4];
        Cs[n4+0][t] = v.x; Cs[n4+1][t] = v.y;
        Cs[n4+2][t] = v.z; Cs[n4+3][t] = v.w;
    }
    const float* Sb = g_S + (((size_t)bh*NCHUNK + ck)*HEADDIM)*DSTATE;
    #pragma unroll
    for (int q = tid; q < 48*16; q += 256) {
        int p  = q >> 4;
        int n4 = (q & 15) << 2;
        float4 v = *(const float4*)&Sb[(size_t)p*DSTATE + n4];
        Hs[n4+0][p] = v.x; Hs[n4+1][p] = v.y;
        Hs[n4+2][p] = v.z; Hs[n4+3][p] = v.w;
    }
    if (tid < 64)
        Ls[tid] = g_LAM[(size_t)(bl0 + tid)*NHEADS + h];
    __syncthreads();

    int tx = tid & 15, ty = tid >> 4;
    int pp = tx*3, tt = ty*4;

    float acc[4][3];
    #pragma unroll
    for (int i = 0; i < 4; i++)
        #pragma unroll
        for (int j = 0; j < 3; j++) acc[i][j] = 0.f;

    #pragma unroll 4
    for (int n = 0; n < 64; n++) {
        float4 c = *(const float4*)&Cs[n][tt];
        float ca[4] = {c.x, c.y, c.z, c.w};
        float hh0 = Hs[n][pp], hh1 = Hs[n][pp+1], hh2 = Hs[n][pp+2];
        #pragma unroll
        for (int i = 0; i < 4; i++) {
            acc[i][0] = fmaf(ca[i], hh0, acc[i][0]);
            acc[i][1] = fmaf(ca[i], hh1, acc[i][1]);
            acc[i][2] = fmaf(ca[i], hh2, acc[i][2]);
        }
    }

    #pragma unroll
    for (int i = 0; i < 4; i++) {
        float lam = Ls[tt + i];
        float* yr = g_Y + (size_t)(bl0 + tt + i)*DINNER + h*HEADDIM + pp;
        #pragma unroll
        for (int j = 0; j < 3; j++)
            yr[j] = fmaf(lam, acc[i][j], yr[j]);
    }
}

// ---------------- gated RMSNorm ------------------------------------------
__global__ __launch_bounds__(128)
void k_gated_rms(const float* __restrict__ norm_w) {
    int bl = blockIdx.x;
    int t  = threadIdx.x;
    int lane = t & 31, wid = t >> 5;
    __shared__ float sh[4];
    float v[3];
    float ss = 0.f;
    #pragma unroll
    for (int j = 0; j < 3; j++) {
        int d = t + j*128;
        float y = g_Y[(size_t)bl*DINNER + d];
        float z = g_ZX[(size_t)bl*DINPROJ + d];
        y *= z * sigf(z);
        v[j] = y;
        ss = fmaf(y, y, ss);
    }
    #pragma unroll
    for (int o = 16; o > 0; o >>= 1) ss += __shfl_xor_sync(0xffffffffu, ss, o);
    if (lane == 0) sh[wid] = ss;
    __syncthreads();
    ss = sh[0] + sh[1] + sh[2] + sh[3];
    float rms = rsqrtf(ss * (1.f/DINNER) + 1e-5f);
    #pragma unroll
    for (int j = 0; j < 3; j++) {
        int d = t + j*128;
        g_Y[(size_t)bl*DINNER + d] = v[j] * rms * norm_w[d];
    }
}

// ---------------- residual add + layernorm -> X --------------------------
__global__ __launch_bounds__(192)
void k_res_ln(const float* __restrict__ ln_w, const float* __restrict__ ln_b) {
    int bl = blockIdx.x;
    int d  = threadIdx.x;
    int lane = d & 31, wid = d >> 5;
    __shared__ float shs[6], shq[6];
    float x = g_O[(size_t)bl*DMODEL + d] + g_X[(size_t)bl*DMODEL + d];
    float s = x, q = x*x;
    #pragma unroll
    for (int o = 16; o > 0; o >>= 1) {
        s += __shfl_xor_sync(0xffffffffu, s, o);
        q += __shfl_xor_sync(0xffffffffu, q, o);
    }
    if (lane == 0) { shs[wid] = s; shq[wid] = q; }
    __syncthreads();
    s = 0.f; q = 0.f;
    #pragma unroll
    for (int i = 0; i < 6; i++) { s += shs[i]; q += shq[i]; }
    float mu  = s * (1.f/DMODEL);
    float var = q * (1.f/DMODEL) - mu*mu;
    g_X[(size_t)bl*DMODEL + d] = (x - mu) * rsqrtf(var + 1e-5f) * ln_w[d] + ln_b[d];
}

// ---------------- output linear ------------------------------------------
__global__ __launch_bounds__(192)
void k_final(const float* __restrict__ w, const float* __restrict__ bias,
             float* __restrict__ out) {
    int bl = blockIdx.x;
    int d  = threadIdx.x;
    int lane = d & 31, wid = d >> 5;
    int b = bl / SEQL, l = bl % SEQL;
    __shared__ float sh[6][4];
    float x = g_X[(size_t)bl*DMODEL + d];
    float p0 = x * w[0*DMODEL + d];
    float p1 = x * w[1*DMODEL + d];
    float p2 = x * w[2*DMODEL + d];
    float p3 = x * w[3*DMODEL + d];
    #pragma unroll
    for (int o = 16; o > 0; o >>= 1) {
        p0 += __shfl_xor_sync(0xffffffffu, p0, o);
        p1 += __shfl_xor_sync(0xffffffffu, p1, o);
        p2 += __shfl_xor_sync(0xffffffffu, p2, o);
        p3 += __shfl_xor_sync(0xffffffffu, p3, o);
    }
    if (lane == 0) { sh[wid][0]=p0; sh[wid][1]=p1; sh[wid][2]=p2; sh[wid][3]=p3; }
    __syncthreads();
    if (d < 4) {
        float s = 0.f;
        #pragma unroll
        for (int i = 0; i < 6; i++) s += sh[i][d];
        out[(size_t)b*4*SEQL + (size_t)d*SEQL + l] = s + bias[d];
    }
}

// ---------------- driver --------------------------------------------------
extern "C" void kernel_launch(void* const* d_in, const int* in_sizes, int n_in,
                              void* d_out, int out_size) {
    const float* inp      = (const float*)d_in[0];
    const float* lin_in_w = (const float*)d_in[1];
    const float* lin_in_b = (const float*)d_in[2];
    const float* in_w     = (const float*)d_in[3];
    const float* conv_w   = (const float*)d_in[4];
    const float* conv_b   = (const float*)d_in[5];
    const float* dt_bias  = (const float*)d_in[6];
    const float* A_log    = (const float*)d_in[7];
    const float* Dv       = (const float*)d_in[8];
    const float* norm_w   = (const float*)d_in[9];
    const float* out_w    = (const float*)d_in[10];
    const float* ln_w     = (const float*)d_in[11];
    const float* ln_b     = (const float*)d_in[12];
    const float* lo_w     = (const float*)d_in[13];
    const float* lo_b     = (const float*)d_in[14];
    float* out = (float*)d_out;

    static bool attr_set = false;
    if (!attr_set) {
        cudaFuncSetAttribute(k_mma, cudaFuncAttributeMaxDynamicSharedMemorySize,
                             (int)MMA_SMEM);
        cudaFuncSetAttribute(k_scan_blk, cudaFuncAttributeMaxDynamicSharedMemorySize,
                             (int)SCAN_SMEM);
        attr_set = true;
    }

    const int scan_blocks = BATCHN*NHEADS*NCHUNK;   // 2048
    const int corr_blocks = BATCHN*NHEADS*NCHUNK;

    k_lin_in<<<(BL*DMODEL + 255)/256, 256>>>(inp, lin_in_w, lin_in_b);

    for (int layer = 0; layer < NLAYERS; layer++) {
        const float* in_w_l = in_w + (size_t)layer*DINPROJ*DMODEL;
        {
            dim3 grid(896/128, BL/128);
            k_mma<<<grid, 256, MMA_SMEM>>>(in_w_l, 0, 896, DMODEL, DINPROJ);
        }
        k_convdt<<<CONV_BLKS + BL/8, 256>>>(
            conv_w + (size_t)layer*CONVDIM*4,
            conv_b + (size_t)layer*CONVDIM,
            dt_bias + layer*NHEADS,
            A_log + layer*NHEADS,
            in_w_l);
        k_scan_blk<<<scan_blocks, 384, SCAN_SMEM>>>(Dv + layer*NHEADS);
        k_chunk_seq<<<(BATCHN*NHEADS*HEADDIM*DSTATE + 255)/256, 256>>>();
        k_corr<<<corr_blocks, 256>>>();
        k_gated_rms<<<BL, 128>>>(norm_w + (size_t)layer*DINNER);
        {
            dim3 grid((DMODEL + 127)/128, BL/128);
            k_mma<<<grid, 256, MMA_SMEM>>>(out_w + (size_t)layer*DMODEL*DINNER, 1,
                                           DMODEL, DINNER, DMODEL);
        }
        k_res_ln<<<BL, 192>>>(ln_w + (size_t)layer*DMODEL,
                              ln_b + (size_t)layer*DMODEL);
    }

    k_final<<<BL, 192>>>(lo_w, lo_b, out);
}